// round 1
// baseline (speedup 1.0000x reference)
#include <cuda_runtime.h>
#include <cstdint>

// Problem constants (fixed shapes for this problem instance)
#define Lc     2048
#define Bc     2
#define Hc     32
#define Pc     64
#define Nc     128
#define DPROJ  4384      // 2*d_inner + 2*dstate + nheads
#define DCONVC 2304      // d_inner + 2*dstate
#define DINNER 2048

// ---------------- scratch (static device globals; no runtime alloc) ---------
// xg: per (b,h,pchunk): [t][p_local][2] = {x, silu(z)} interleaved -> streamed
__device__ __align__(16) float g_xg[(size_t)Bc * Hc * 2 * Lc * 64];   // 64 MB
__device__ __align__(16) float g_B [(size_t)Bc * Lc * Nc];            // 2 MB
__device__ __align__(16) float g_C [(size_t)Bc * Lc * Nc];            // 2 MB
__device__ __align__(16) float g_dtA[(size_t)Bc * Hc * Lc * 2];       // 1 MB

// ---------------- packed f32x2 helpers --------------------------------------
__device__ __forceinline__ uint64_t pk2(float lo, float hi) {
    uint64_t r;
    asm("mov.b64 %0, {%1,%2};" : "=l"(r) : "f"(lo), "f"(hi));
    return r;
}
__device__ __forceinline__ void unpk2(uint64_t v, float& lo, float& hi) {
    asm("mov.b64 {%0,%1}, %2;" : "=f"(lo), "=f"(hi) : "l"(v));
}
__device__ __forceinline__ uint64_t f2fma(uint64_t a, uint64_t b, uint64_t c) {
    uint64_t d;
    asm("fma.rn.f32x2 %0, %1, %2, %3;" : "=l"(d) : "l"(a), "l"(b), "l"(c));
    return d;
}
__device__ __forceinline__ uint64_t f2mul(uint64_t a, uint64_t b) {
    uint64_t d;
    asm("mul.rn.f32x2 %0, %1, %2;" : "=l"(d) : "l"(a), "l"(b));
    return d;
}
__device__ __forceinline__ void cpa16(void* sm, const void* gm) {
    unsigned sa = (unsigned)__cvta_generic_to_shared(sm);
    asm volatile("cp.async.cg.shared.global [%0], [%1], 16;" :: "r"(sa), "l"(gm));
}

// ---------------- pre-pass: conv + SiLU + dt/dA + gate, routed to scratch ---
__global__ void prepass_kernel(const float* __restrict__ zx,
                               const float* __restrict__ cw,
                               const float* __restrict__ cb,
                               const float* __restrict__ dt_bias,
                               const float* __restrict__ a_log,
                               const float* __restrict__ dt_scale) {
    int bt  = blockIdx.x;            // b*L + t
    int b   = bt >> 11;
    int t   = bt & (Lc - 1);
    int idx = blockIdx.y * 256 + threadIdx.x;   // "work channel"
    if (idx >= DPROJ) return;

    const float* row = zx + (size_t)bt * DPROJ;

    if (idx < DINNER) {
        // gate path: g = silu(z)
        float z = row[idx];
        float g = z / (1.f + expf(-z));
        int h = idx >> 6, p = idx & 63;
        g_xg[(((((size_t)b * Hc + h) * 2 + (p >> 5)) * Lc) + t) * 64 + (p & 31) * 2 + 1] = g;
    } else if (idx < DINNER + DCONVC) {
        // depthwise causal conv (k=4) + bias + silu; channel column in zx == idx
        int cc = idx - DINNER;
        float acc = cb[cc];
        const float* w = cw + cc * 4;
        #pragma unroll
        for (int i = 0; i < 4; ++i) {
            int l2 = t - 3 + i;
            if (l2 >= 0) acc += w[i] * zx[((size_t)(b * Lc + l2)) * DPROJ + idx];
        }
        float v = acc / (1.f + expf(-acc));
        if (cc < DINNER) {
            int h = cc >> 6, p = cc & 63;
            g_xg[(((((size_t)b * Hc + h) * 2 + (p >> 5)) * Lc) + t) * 64 + (p & 31) * 2] = v;
        } else if (cc < DINNER + Nc) {
            g_B[((size_t)(b * Lc + t)) * Nc + (cc - DINNER)] = v;
        } else {
            g_C[((size_t)(b * Lc + t)) * Nc + (cc - DINNER - Nc)] = v;
        }
    } else {
        // dt path: one per head
        int h = idx - (DINNER + DCONVC);
        float v  = row[DPROJ - Hc + h] * dt_scale[h] + dt_bias[h];
        float dt = (v > 20.f) ? v : log1pf(expf(v));
        dt = fminf(fmaxf(dt, 0.f), 100.f);
        float A  = -expf(a_log[h]);
        float dA = expf(dt * A);
        size_t o = ((size_t)(b * Hc + h) * Lc + t) * 2;
        g_dtA[o]     = dt;
        g_dtA[o + 1] = dA;
    }
}

// ---------------- scan kernel -----------------------------------------------
// grid = 128 blocks: (b,h,pchunk).  block = 128 threads: 32 p_local x 4 j.
// Thread state: 32 n-values (8 float4 chunks, strided by j) as 16 packed f32x2.
#define NSTAGE 4
#define SSTEPS 8
#define NITER  (Lc / SSTEPS)   // 256

__global__ void __launch_bounds__(128, 1)
scan_kernel(const float* __restrict__ d_param,
            const float* __restrict__ init_state,
            float* __restrict__ out) {
    const int bid = blockIdx.x;
    const int b  = bid >> 6;
    const int h  = (bid >> 1) & 31;
    const int pc = bid & 1;
    const int tid = threadIdx.x;
    const int pl  = tid >> 2;      // p_local 0..31
    const int j   = tid & 3;       // n-slice 0..3
    const int p   = pc * 32 + pl;

    __shared__ __align__(16) float sB  [NSTAGE][SSTEPS][Nc];
    __shared__ __align__(16) float sC  [NSTAGE][SSTEPS][Nc];
    __shared__ __align__(16) float sXG [NSTAGE][SSTEPS][64];
    __shared__ __align__(16) float sdtA[NSTAGE][SSTEPS][2];

    const float4* gB   = (const float4*)(g_B  + (size_t)b * Lc * Nc);
    const float4* gC   = (const float4*)(g_C  + (size_t)b * Lc * Nc);
    const float4* gXG  = (const float4*)(g_xg + (size_t)((b * Hc + h) * 2 + pc) * Lc * 64);
    const float4* gdtA = (const float4*)(g_dtA + (size_t)(b * Hc + h) * Lc * 2);

    // stage issue: B/C = 256 float4 each, XG = 128 float4, dtA = 4 float4
    auto issue_stage = [&](int k, int buf) {
        const float4* srcB  = gB  + (size_t)k * 256;
        const float4* srcC  = gC  + (size_t)k * 256;
        const float4* srcXG = gXG + (size_t)k * 128;
        #pragma unroll
        for (int r = 0; r < 2; ++r) {
            cpa16(&sB[buf][0][(tid + r * 128) * 4], srcB + tid + r * 128);
            cpa16(&sC[buf][0][(tid + r * 128) * 4], srcC + tid + r * 128);
        }
        cpa16(&sXG[buf][0][tid * 4], srcXG + tid);
        if (tid < 4) cpa16(&sdtA[buf][0][tid * 4], gdtA + (size_t)k * 4 + tid);
    };

    // init state from initial_state[b,h,p,:]
    uint64_t s2[16];
    const float4* ist = (const float4*)(init_state + ((size_t)((b * Hc + h) * Pc + p)) * Nc);
    #pragma unroll
    for (int i = 0; i < 8; ++i) {
        float4 v = ist[j + i * 4];
        s2[2 * i]     = pk2(v.x, v.y);
        s2[2 * i + 1] = pk2(v.z, v.w);
    }
    const float Dh = d_param[h];

    // prologue: fill the ring
    #pragma unroll
    for (int s = 0; s < NSTAGE; ++s) {
        issue_stage(s, s);
        asm volatile("cp.async.commit_group;");
    }

    float* outbase = out + (size_t)b * Lc * DINNER + h * 64 + p;

    for (int k = 0; k < NITER; ++k) {
        asm volatile("cp.async.wait_group %0;" :: "n"(NSTAGE - 1));
        __syncthreads();
        const int buf = k & (NSTAGE - 1);

        #pragma unroll
        for (int u = 0; u < SSTEPS; ++u) {
            float2 da = *(const float2*)&sdtA[buf][u][0];       // {dt, dA} broadcast
            float2 xg = *(const float2*)&sXG[buf][u][pl * 2];   // {x, silu(z)}
            float dtx = da.x * xg.x;
            uint64_t dtx2 = pk2(dtx, dtx);
            uint64_t dA2  = pk2(da.y, da.y);
            uint64_t acc0 = 0, acc1 = 0;
            #pragma unroll
            for (int i = 0; i < 8; ++i) {
                int ch = j + i * 4;
                ulonglong2 b2 = *(const ulonglong2*)&sB[buf][u][ch * 4];
                ulonglong2 c2 = *(const ulonglong2*)&sC[buf][u][ch * 4];
                s2[2 * i]     = f2fma(dA2, s2[2 * i],     f2mul(dtx2, b2.x));
                s2[2 * i + 1] = f2fma(dA2, s2[2 * i + 1], f2mul(dtx2, b2.y));
                acc0 = f2fma(s2[2 * i],     c2.x, acc0);
                acc1 = f2fma(s2[2 * i + 1], c2.y, acc1);
            }
            float a0lo, a0hi, a1lo, a1hi;
            unpk2(acc0, a0lo, a0hi);
            unpk2(acc1, a1lo, a1hi);
            float y = (a0lo + a0hi) + (a1lo + a1hi);
            y += __shfl_xor_sync(0xffffffffu, y, 1);
            y += __shfl_xor_sync(0xffffffffu, y, 2);
            if (j == 0) {
                int t = k * SSTEPS + u;
                outbase[(size_t)t * DINNER] = (y + Dh * xg.x) * xg.y;
            }
        }
        __syncthreads();
        int kn = k + NSTAGE;
        if (kn < NITER) issue_stage(kn, buf);
        asm volatile("cp.async.commit_group;");
    }
}

// ---------------- launch -----------------------------------------------------
extern "C" void kernel_launch(void* const* d_in, const int* in_sizes, int n_in,
                              void* d_out, int out_size) {
    const float* zxbcdt     = (const float*)d_in[0];
    const float* conv_w     = (const float*)d_in[1];
    const float* conv_b     = (const float*)d_in[2];
    const float* dt_bias    = (const float*)d_in[3];
    const float* a_log      = (const float*)d_in[4];
    const float* d_param    = (const float*)d_in[5];
    const float* dt_scale   = (const float*)d_in[6];
    const float* init_state = (const float*)d_in[7];
    float* out = (float*)d_out;

    dim3 pg(Bc * Lc, (DPROJ + 255) / 256);
    prepass_kernel<<<pg, 256>>>(zxbcdt, conv_w, conv_b, dt_bias, a_log, dt_scale);
    scan_kernel<<<Bc * Hc * 2, 128>>>(d_param, init_state, out);
}